// round 1
// baseline (speedup 1.0000x reference)
#include <cuda_runtime.h>

#define NB   16384
#define RNN  256
#define LAT  64
#define ATT  64
#define NA   32
#define HID  256
#define NF   320   // 256 xh features + 32 q features + 32 score features

// ---------------- GEMM tiling ----------------
#define BM 128
#define BN 64
#define BK 32
#define ASTR 132   // padded stride for As[k][m]
#define BSTR 68    // padded stride for Bs[k][n]

// ---------------- device scratch / precomputed ----------------
__device__ __align__(16) float g_Wt[RNN * NF];       // packed weights, K-major: [k][feature]
__device__ __align__(16) float g_bias[NF];           // 0 for xh, qbias, scbias
__device__ __align__(16) float g_query[NA * ATT];    // query = act @ query_w.T + query_b
__device__ __align__(16) float g_ya[NA * HID];       // act @ w1_a.T + msg_b1
__device__ __align__(16) float g_w2t[HID * NA];      // msg_w2 transposed
__device__ __align__(16) float g_msb[NA];            // 32 * msg_b2
__device__ __align__(16) float g_Y[(size_t)NB * NF]; // GEMM output scratch (21 MB)

// ================= setup 1: tiny per-action precompute (1 block) =================
__global__ void setup1_kernel(const float* __restrict__ act,
                              const float* __restrict__ qfb,
                              const float* __restrict__ b2,
                              const float* __restrict__ kb,
                              const float* __restrict__ qw,
                              const float* __restrict__ qb) {
    __shared__ float s_act[NA * LAT];
    int tid = threadIdx.x;
    for (int i = tid; i < NA * LAT; i += blockDim.x) s_act[i] = act[i];
    __syncthreads();
    // query[a][t] = sum_l act[a][l] * query_w[t][l] + query_b[t]
    for (int i = tid; i < NA * ATT; i += blockDim.x) {
        int a = i / ATT, t = i % ATT;
        float s = qb[t];
        for (int l = 0; l < LAT; l++) s += s_act[a * LAT + l] * qw[t * LAT + l];
        g_query[a * ATT + t] = s;
    }
    __syncthreads();
    // biases for packed GEMM columns
    for (int i = tid; i < NF; i += blockDim.x) {
        float v = 0.f;
        if (i >= HID && i < HID + NA) {            // q bias = act[a] . q_fc_b
            int a = i - HID;
            float s = 0.f;
            for (int l = 0; l < LAT; l++) s += s_act[a * LAT + l] * qfb[l];
            v = s;
        } else if (i >= HID + NA) {                // score bias = (query[a] . key_b)/8
            int a = i - HID - NA;
            float s = 0.f;
            for (int t = 0; t < ATT; t++) s += g_query[a * ATT + t] * kb[t];
            v = s * 0.125f;
        }
        g_bias[i] = v;
    }
    for (int i = tid; i < NA; i += blockDim.x) g_msb[i] = 32.f * b2[i];
}

// ================= setup 2: pack weights (grid-stride) =================
__global__ void setup2_kernel(const float* __restrict__ act,
                              const float* __restrict__ qfw,
                              const float* __restrict__ w1,
                              const float* __restrict__ b1,
                              const float* __restrict__ w2,
                              const float* __restrict__ kw) {
    int idx0 = blockIdx.x * blockDim.x + threadIdx.x;
    int stride = gridDim.x * blockDim.x;
    // g_Wt[k][j]: j<256 -> w1_h[j][k]; 256..287 -> Mq[a][k]; 288..319 -> Msc[a][k]
    for (int i = idx0; i < RNN * NF; i += stride) {
        int k = i / NF, j = i % NF;
        float v;
        if (j < HID) {
            v = w1[j * (RNN + LAT) + k];
        } else if (j < HID + NA) {
            int a = j - HID;
            float s = 0.f;
            for (int l = 0; l < LAT; l++) s += act[a * LAT + l] * qfw[l * RNN + k];
            v = s;
        } else {
            int a = j - HID - NA;
            float s = 0.f;
            for (int t = 0; t < ATT; t++) s += g_query[a * ATT + t] * kw[t * RNN + k];
            v = s * 0.125f;
        }
        g_Wt[k * NF + j] = v;
    }
    // ya[a][h] = act[a] . w1_a[h] + b1[h];  w2t[h][a] = w2[a][h]
    for (int i = idx0; i < NA * HID; i += stride) {
        int a = i / HID, hh = i % HID;
        float s = b1[hh];
        for (int l = 0; l < LAT; l++) s += act[a * LAT + l] * w1[hh * (RNN + LAT) + RNN + l];
        g_ya[a * HID + hh] = s;
        g_w2t[hh * NA + a] = w2[a * HID + hh];
    }
}

// ================= main GEMM: Y = h @ Wt + bias =================
__global__ void __launch_bounds__(256) gemm_kernel(const float* __restrict__ hmat) {
    __shared__ __align__(16) float As[BK * ASTR];
    __shared__ __align__(16) float Bs[BK * BSTR];
    int tid = threadIdx.x;
    int tx = tid & 15, ty = tid >> 4;
    int m0 = blockIdx.y * BM;
    int n0 = blockIdx.x * BN;
    float acc[8][4];
#pragma unroll
    for (int i = 0; i < 8; i++)
#pragma unroll
        for (int j = 0; j < 4; j++) acc[i][j] = 0.f;

    int a_row = tid >> 3;   // 0..31
    int a_c4  = tid & 7;    // k-quad 0..7
    int b_k   = tid >> 4;   // 0..15
    int b_j4  = tid & 15;   // n-quad 0..15

    for (int k0 = 0; k0 < RNN; k0 += BK) {
        // A tile: 128 rows x 32 k, transposed into As[k][m]
#pragma unroll
        for (int r = 0; r < 4; r++) {
            int row = a_row + 32 * r;
            float4 v = *(const float4*)&hmat[(size_t)(m0 + row) * RNN + k0 + a_c4 * 4];
            As[(a_c4 * 4 + 0) * ASTR + row] = v.x;
            As[(a_c4 * 4 + 1) * ASTR + row] = v.y;
            As[(a_c4 * 4 + 2) * ASTR + row] = v.z;
            As[(a_c4 * 4 + 3) * ASTR + row] = v.w;
        }
        // B tile: g_Wt is K-major -> direct vector copy
#pragma unroll
        for (int r = 0; r < 2; r++) {
            int k = b_k + 16 * r;
            float4 v = *(const float4*)&g_Wt[(k0 + k) * NF + n0 + b_j4 * 4];
            *(float4*)&Bs[k * BSTR + b_j4 * 4] = v;
        }
        __syncthreads();
#pragma unroll
        for (int k = 0; k < BK; k++) {
            float a[8], bb[4];
            *(float4*)&a[0] = *(const float4*)&As[k * ASTR + ty * 8];
            *(float4*)&a[4] = *(const float4*)&As[k * ASTR + ty * 8 + 4];
            *(float4*)&bb[0] = *(const float4*)&Bs[k * BSTR + tx * 4];
#pragma unroll
            for (int i = 0; i < 8; i++)
#pragma unroll
                for (int j = 0; j < 4; j++)
                    acc[i][j] = fmaf(a[i], bb[j], acc[i][j]);
        }
        __syncthreads();
    }
    float4 bv = *(const float4*)&g_bias[n0 + tx * 4];
#pragma unroll
    for (int i = 0; i < 8; i++) {
        int row = m0 + ty * 8 + i;
        float4 o;
        o.x = acc[i][0] + bv.x;
        o.y = acc[i][1] + bv.y;
        o.z = acc[i][2] + bv.z;
        o.w = acc[i][3] + bv.w;
        *(float4*)&g_Y[(size_t)row * NF + n0 + tx * 4] = o;
    }
}

// ================= epilogue: leaky-sum, msg GEMV, softmax, combine =================
#define RPB 32  // rows per block (8 warps x 4 rows)
#define EPI_SMEM ((NA * HID + HID * NA + 8 * HID) * 4)

__global__ void __launch_bounds__(256) epilogue_kernel(float* __restrict__ out) {
    extern __shared__ __align__(16) float smem[];
    float* s_ya  = smem;                 // 32x256
    float* s_w2t = smem + NA * HID;      // 256x32
    float* s_S   = smem + 2 * NA * HID;  // 8 warps x 256
    __shared__ float s_msb[NA];
    int tid = threadIdx.x;
    {
        const float4* g1 = (const float4*)g_ya;
        const float4* g2 = (const float4*)g_w2t;
        float4* d1 = (float4*)s_ya;
        float4* d2 = (float4*)s_w2t;
        for (int i = tid; i < NA * HID / 4; i += 256) { d1[i] = g1[i]; d2[i] = g2[i]; }
    }
    if (tid < NA) s_msb[tid] = g_msb[tid];
    __syncthreads();

    int w = tid >> 5, lane = tid & 31;
    int b0 = blockIdx.x * RPB;
    for (int rr = 0; rr < RPB / 8; rr++) {
        int b = b0 + rr * 8 + w;
        const float* Yrow = &g_Y[(size_t)b * NF];
        float xh[8];
        *(float4*)&xh[0] = *(const float4*)&Yrow[lane * 8];
        *(float4*)&xh[4] = *(const float4*)&Yrow[lane * 8 + 4];
        float qv = Yrow[HID + lane];
        float sc = Yrow[HID + NA + lane];

        // S[h] = sum_a max(xh+ya, 0.01*(xh+ya))
        float Sv[8];
#pragma unroll
        for (int i = 0; i < 8; i++) Sv[i] = 0.f;
#pragma unroll
        for (int a = 0; a < NA; a++) {
            float y[8];
            *(float4*)&y[0] = *(const float4*)&s_ya[a * HID + lane * 8];
            *(float4*)&y[4] = *(const float4*)&s_ya[a * HID + lane * 8 + 4];
#pragma unroll
            for (int i = 0; i < 8; i++) {
                float pre = xh[i] + y[i];
                Sv[i] += fmaxf(pre, 0.01f * pre);
            }
        }
        *(float4*)&s_S[w * HID + lane * 8]     = *(float4*)&Sv[0];
        *(float4*)&s_S[w * HID + lane * 8 + 4] = *(float4*)&Sv[4];
        __syncwarp();

        // msg_sum[a] = S . w2t[:,a] + 32*b2[a]
        float m = s_msb[lane];
#pragma unroll 8
        for (int hh = 0; hh < HID; hh += 4) {
            float4 sv = *(const float4*)&s_S[w * HID + hh];
            m = fmaf(sv.x, s_w2t[(hh + 0) * NA + lane], m);
            m = fmaf(sv.y, s_w2t[(hh + 1) * NA + lane], m);
            m = fmaf(sv.z, s_w2t[(hh + 2) * NA + lane], m);
            m = fmaf(sv.w, s_w2t[(hh + 3) * NA + lane], m);
        }

        // softmax over 32 lanes
        float mx = sc;
#pragma unroll
        for (int o = 16; o > 0; o >>= 1) mx = fmaxf(mx, __shfl_xor_sync(0xffffffffu, mx, o));
        float e = __expf(sc - mx);
        float se = e;
#pragma unroll
        for (int o = 16; o > 0; o >>= 1) se += __shfl_xor_sync(0xffffffffu, se, o);

        out[(size_t)b * NA + lane] = qv + (e / se) * m;
        __syncwarp();
    }
}

// ================= launch =================
extern "C" void kernel_launch(void* const* d_in, const int* in_sizes, int n_in,
                              void* d_out, int out_size) {
    const float* h   = (const float*)d_in[0];
    const float* act = (const float*)d_in[1];
    const float* qfw = (const float*)d_in[2];
    const float* qfb = (const float*)d_in[3];
    const float* w1  = (const float*)d_in[4];
    const float* b1  = (const float*)d_in[5];
    const float* w2  = (const float*)d_in[6];
    const float* b2  = (const float*)d_in[7];
    const float* kw  = (const float*)d_in[8];
    const float* kb  = (const float*)d_in[9];
    const float* qw  = (const float*)d_in[10];
    const float* qb  = (const float*)d_in[11];
    float* out = (float*)d_out;

    (void)in_sizes; (void)n_in; (void)out_size;

    setup1_kernel<<<1, 256>>>(act, qfb, b2, kb, qw, qb);
    setup2_kernel<<<64, 256>>>(act, qfw, w1, b1, w2, kw);

    dim3 ggrid(NF / BN, NB / BM);
    gemm_kernel<<<ggrid, 256>>>(h);

    cudaFuncSetAttribute(epilogue_kernel, cudaFuncAttributeMaxDynamicSharedMemorySize, EPI_SMEM);
    epilogue_kernel<<<NB / RPB, 256, EPI_SMEM>>>(out);
}

// round 3
// speedup vs baseline: 1.4330x; 1.4330x over previous
#include <cuda_runtime.h>
#include <cuda_bf16.h>
#include <cstdint>

#define NB   16384
#define RNN  256
#define LAT  64
#define ATT  64
#define NA   32
#define HID  256
#define NF   320   // 256 xh + 32 q + 32 score

// ======================= device globals =======================
__device__ __align__(16) float g_bias[NF];
__device__ __align__(16) float g_query[NA * ATT];
__device__ __align__(16) float g_ya[NA * HID];
__device__ __align__(16) __nv_bfloat16 g_Ah[(size_t)NB * RNN];
__device__ __align__(16) __nv_bfloat16 g_Al[(size_t)NB * RNN];
__device__ __align__(16) __nv_bfloat16 g_Bh[RNN * NF];
__device__ __align__(16) __nv_bfloat16 g_Bl[RNN * NF];
__device__ __align__(16) float g_Y[(size_t)NB * NF];

// ======================= asm helpers =======================
__device__ __forceinline__ uint32_t smem_u32(const void* p) {
    uint32_t a;
    asm("{ .reg .u64 t; cvta.to.shared.u64 t, %1; cvt.u32.u64 %0, t; }" : "=r"(a) : "l"(p));
    return a;
}
__device__ __forceinline__ void cp16(uint32_t dst, const void* src) {
    asm volatile("cp.async.ca.shared.global [%0], [%1], 16;" :: "r"(dst), "l"(src));
}
#define CP_COMMIT asm volatile("cp.async.commit_group;" ::: "memory")
#define CP_WAIT0  asm volatile("cp.async.wait_group 0;" ::: "memory")
#define CP_WAIT1  asm volatile("cp.async.wait_group 1;" ::: "memory")

__device__ __forceinline__ void ldsm_x4(uint32_t* r, uint32_t a) {
    asm volatile("ldmatrix.sync.aligned.m8n8.x4.shared.b16 {%0,%1,%2,%3}, [%4];"
        : "=r"(r[0]), "=r"(r[1]), "=r"(r[2]), "=r"(r[3]) : "r"(a));
}
__device__ __forceinline__ void ldsm_x4t(uint32_t* r, uint32_t a) {
    asm volatile("ldmatrix.sync.aligned.m8n8.x4.trans.shared.b16 {%0,%1,%2,%3}, [%4];"
        : "=r"(r[0]), "=r"(r[1]), "=r"(r[2]), "=r"(r[3]) : "r"(a));
}
__device__ __forceinline__ void mma16816(float* c, const uint32_t* a, const uint32_t* b) {
    asm volatile("mma.sync.aligned.m16n8k16.row.col.f32.bf16.bf16.f32 "
        "{%0,%1,%2,%3}, {%4,%5,%6,%7}, {%8,%9}, {%0,%1,%2,%3};"
        : "+f"(c[0]), "+f"(c[1]), "+f"(c[2]), "+f"(c[3])
        : "r"(a[0]), "r"(a[1]), "r"(a[2]), "r"(a[3]), "r"(b[0]), "r"(b[1]));
}

// ======================= setup 1 =======================
__global__ void setup1_kernel(const float* __restrict__ act,
                              const float* __restrict__ qfb,
                              const float* __restrict__ kb,
                              const float* __restrict__ qw,
                              const float* __restrict__ qb) {
    __shared__ float s_act[NA * LAT];
    int tid = threadIdx.x;
    for (int i = tid; i < NA * LAT; i += blockDim.x) s_act[i] = act[i];
    __syncthreads();
    for (int i = tid; i < NA * ATT; i += blockDim.x) {
        int a = i / ATT, t = i % ATT;
        float s = qb[t];
        for (int l = 0; l < LAT; l++) s += s_act[a * LAT + l] * qw[t * LAT + l];
        g_query[a * ATT + t] = s;
    }
    __syncthreads();
    for (int i = tid; i < NF; i += blockDim.x) {
        float v = 0.f;
        if (i >= HID && i < HID + NA) {
            int a = i - HID;
            float s = 0.f;
            for (int l = 0; l < LAT; l++) s += s_act[a * LAT + l] * qfb[l];
            v = s;
        } else if (i >= HID + NA) {
            int a = i - HID - NA;
            float s = 0.f;
            for (int t = 0; t < ATT; t++) s += g_query[a * ATT + t] * kb[t];
            v = s * 0.125f;
        }
        g_bias[i] = v;
    }
}

// ======================= setup 2: B pack (bf16 hi/lo) + ya =======================
__global__ void setup2_kernel(const float* __restrict__ act,
                              const float* __restrict__ qfw,
                              const float* __restrict__ w1,
                              const float* __restrict__ b1,
                              const float* __restrict__ kw) {
    int idx0 = blockIdx.x * blockDim.x + threadIdx.x;
    int stride = gridDim.x * blockDim.x;
    for (int i = idx0; i < RNN * NF; i += stride) {
        int k = i / NF, j = i % NF;
        float v;
        if (j < HID) {
            v = w1[j * (RNN + LAT) + k];
        } else if (j < HID + NA) {
            int a = j - HID;
            float s = 0.f;
            for (int l = 0; l < LAT; l++) s += act[a * LAT + l] * qfw[l * RNN + k];
            v = s;
        } else {
            int a = j - HID - NA;
            float s = 0.f;
            for (int t = 0; t < ATT; t++) s += g_query[a * ATT + t] * kw[t * RNN + k];
            v = s * 0.125f;
        }
        __nv_bfloat16 hb = __float2bfloat16_rn(v);
        float lo = v - __bfloat162float(hb);
        g_Bh[i] = hb;
        g_Bl[i] = __float2bfloat16_rn(lo);
    }
    for (int i = idx0; i < NA * HID; i += stride) {
        int a = i / HID, hh = i % HID;
        float s = b1[hh];
        for (int l = 0; l < LAT; l++) s += act[a * LAT + l] * w1[hh * (RNN + LAT) + RNN + l];
        g_ya[a * HID + hh] = s;
    }
}

// ======================= A pack: h -> bf16 hi/lo planes =======================
__global__ void __launch_bounds__(256) apack_kernel(const float* __restrict__ h) {
    int u = blockIdx.x * 256 + threadIdx.x;   // over NB*RNN/8
    int b = u >> 5;
    int k0 = (u & 31) * 8;
    float4 v0 = *(const float4*)&h[(size_t)b * RNN + k0];
    float4 v1 = *(const float4*)&h[(size_t)b * RNN + k0 + 4];
    float v[8] = {v0.x, v0.y, v0.z, v0.w, v1.x, v1.y, v1.z, v1.w};
    uint32_t hw[4], lw[4];
#pragma unroll
    for (int i = 0; i < 4; i++) {
        float a = v[2 * i], bb = v[2 * i + 1];
        __nv_bfloat16 ha = __float2bfloat16_rn(a);
        __nv_bfloat16 hb = __float2bfloat16_rn(bb);
        __nv_bfloat16 la = __float2bfloat16_rn(a - __bfloat162float(ha));
        __nv_bfloat16 lb = __float2bfloat16_rn(bb - __bfloat162float(hb));
        hw[i] = (uint32_t)__bfloat16_as_ushort(ha) | ((uint32_t)__bfloat16_as_ushort(hb) << 16);
        lw[i] = (uint32_t)__bfloat16_as_ushort(la) | ((uint32_t)__bfloat16_as_ushort(lb) << 16);
    }
    size_t off = (size_t)b * RNN + k0;
    *(uint4*)&g_Ah[off] = make_uint4(hw[0], hw[1], hw[2], hw[3]);
    *(uint4*)&g_Al[off] = make_uint4(lw[0], lw[1], lw[2], lw[3]);
}

// ======================= HMMA GEMM: Y = h @ W + bias =======================
// SMEM tile offsets (bytes). A stride 80B (40 bf16), B stride 144B (72 bf16).
#define A_H  0
#define A_L  10240
#define B_H  20480
#define B_L  25088
#define BUFB 29696
#define GEMM_SMEM (2 * BUFB)

__global__ void __launch_bounds__(256, 2) gemm_mma_kernel() {
    extern __shared__ char gsm[];
    uint32_t sb = smem_u32(gsm);
    int tid = threadIdx.x;
    int lane = tid & 31, wid = tid >> 5;
    int wm = wid & 3, wn = wid >> 2;
    int m0 = blockIdx.y * 128;
    int n0 = blockIdx.x * 64;

    float acc[2][4][4];
#pragma unroll
    for (int mt = 0; mt < 2; mt++)
#pragma unroll
        for (int nt = 0; nt < 4; nt++)
#pragma unroll
            for (int i = 0; i < 4; i++) acc[mt][nt][i] = 0.f;

    auto load_tiles = [&](int it, int buf) {
        int k0 = it * 32;
        uint32_t base = sb + buf * BUFB;
#pragma unroll
        for (int i = 0; i < 2; i++) {
            int c = tid + 256 * i;         // 0..511
            int row = c >> 2, ch = c & 3;
            size_t src = (size_t)(m0 + row) * RNN + k0 + ch * 8;
            cp16(base + A_H + row * 80 + ch * 16, g_Ah + src);
            cp16(base + A_L + row * 80 + ch * 16, g_Al + src);
        }
        {
            int row = tid >> 3, ch = tid & 7;
            size_t src = (size_t)(k0 + row) * NF + n0 + ch * 8;
            cp16(base + B_H + row * 144 + ch * 16, g_Bh + src);
            cp16(base + B_L + row * 144 + ch * 16, g_Bl + src);
        }
    };

    auto compute = [&](int buf) {
        uint32_t base = sb + buf * BUFB;
#pragma unroll
        for (int ks = 0; ks < 32; ks += 16) {
            uint32_t ah[2][4], al[2][4], bh[2][4], bl[2][4];
            int arow = (lane & 7) + ((lane >> 3) & 1) * 8;
            int akk = ks + (lane >> 4) * 8;
#pragma unroll
            for (int mt = 0; mt < 2; mt++) {
                uint32_t ao = (wm * 32 + mt * 16 + arow) * 80 + akk * 2;
                ldsm_x4(ah[mt], base + A_H + ao);
                ldsm_x4(al[mt], base + A_L + ao);
            }
            int bk = ks + (lane & 7) + ((lane >> 3) & 1) * 8;
#pragma unroll
            for (int np = 0; np < 2; np++) {
                int bn = wn * 32 + np * 16 + ((lane >> 4) & 1) * 8;
                uint32_t bo = bk * 144 + bn * 2;
                ldsm_x4t(bh[np], base + B_H + bo);
                ldsm_x4t(bl[np], base + B_L + bo);
            }
#pragma unroll
            for (int mt = 0; mt < 2; mt++)
#pragma unroll
                for (int nt = 0; nt < 4; nt++) {
                    int np = nt >> 1, hf = nt & 1;
                    mma16816(acc[mt][nt], ah[mt], &bh[np][hf * 2]);
                    mma16816(acc[mt][nt], al[mt], &bh[np][hf * 2]);
                    mma16816(acc[mt][nt], ah[mt], &bl[np][hf * 2]);
                }
        }
    };

    load_tiles(0, 0);
    CP_COMMIT;
    for (int it = 0; it < 8; it++) {
        if (it + 1 < 8) { load_tiles(it + 1, (it + 1) & 1); CP_COMMIT; CP_WAIT1; }
        else            { CP_WAIT0; }
        __syncthreads();
        compute(it & 1);
        __syncthreads();
    }

    // store with bias
#pragma unroll
    for (int mt = 0; mt < 2; mt++) {
        int row = m0 + wm * 32 + mt * 16 + (lane >> 2);
#pragma unroll
        for (int nt = 0; nt < 4; nt++) {
            int col = n0 + wn * 32 + nt * 8 + (lane & 3) * 2;
            float bx = g_bias[col], by = g_bias[col + 1];
            float2 o0 = make_float2(acc[mt][nt][0] + bx, acc[mt][nt][1] + by);
            float2 o1 = make_float2(acc[mt][nt][2] + bx, acc[mt][nt][3] + by);
            *(float2*)&g_Y[(size_t)row * NF + col] = o0;
            *(float2*)&g_Y[(size_t)(row + 8) * NF + col] = o1;
        }
    }
}

// ======================= epilogue =======================
#define W2STR 260
#define EPI_SMEM ((8192 + NA * W2STR + 8192 + HID) * 4)

__global__ void __launch_bounds__(256) epilogue_kernel(const float* __restrict__ w2,
                                                       const float* __restrict__ b2,
                                                       float* __restrict__ out) {
    extern __shared__ char esm[];
    float* sm = (float*)esm;
    float* s_ya   = sm;
    float* s_w2   = sm + 8192;
    float* s_S    = sm + 8192 + NA * W2STR;
    float* s_ySum = s_S + 8192;
    int tid = threadIdx.x;
    {
        const float4* g = (const float4*)g_ya;
        float4* d = (float4*)s_ya;
        for (int i = tid; i < 2048; i += 256) d[i] = g[i];
        for (int i = tid; i < 2048; i += 256) {
            int a = i >> 6, hh = (i & 63) * 4;
            *(float4*)&s_w2[a * W2STR + hh] = *(const float4*)&w2[a * HID + hh];
        }
    }
    __syncthreads();
    {
        float s = 0.f;
        for (int a = 0; a < NA; a++) s += s_ya[a * HID + tid];
        s_ySum[tid] = s;
    }
    __syncthreads();

    int w = tid >> 5, lane = tid & 31;
    int b0 = blockIdx.x * 32 + w * 4;

    float xh[4][8], qv[4], sc[4];
#pragma unroll
    for (int r = 0; r < 4; r++) {
        const float* Yr = g_Y + (size_t)(b0 + r) * NF;
        *(float4*)&xh[r][0] = *(const float4*)&Yr[lane * 4];
        *(float4*)&xh[r][4] = *(const float4*)&Yr[128 + lane * 4];
        qv[r] = Yr[HID + lane];
        sc[r] = Yr[HID + NA + lane];
    }
    float Sv[4][8];
#pragma unroll
    for (int r = 0; r < 4; r++)
#pragma unroll
        for (int i = 0; i < 8; i++) Sv[r][i] = 0.f;

#pragma unroll 4
    for (int a = 0; a < NA; a++) {
        float y[8];
        *(float4*)&y[0] = *(const float4*)&s_ya[a * HID + lane * 4];
        *(float4*)&y[4] = *(const float4*)&s_ya[a * HID + 128 + lane * 4];
#pragma unroll
        for (int r = 0; r < 4; r++)
#pragma unroll
            for (int i = 0; i < 8; i++)
                Sv[r][i] += fabsf(xh[r][i] + y[i]);
    }
    float ys[8];
    *(float4*)&ys[0] = *(const float4*)&s_ySum[lane * 4];
    *(float4*)&ys[4] = *(const float4*)&s_ySum[128 + lane * 4];
#pragma unroll
    for (int r = 0; r < 4; r++) {
        float o[8];
#pragma unroll
        for (int i = 0; i < 8; i++)
            o[i] = 0.505f * fmaf(32.f, xh[r][i], ys[i]) + 0.495f * Sv[r][i];
        *(float4*)&s_S[(w * 4 + r) * HID + lane * 4]       = *(float4*)&o[0];
        *(float4*)&s_S[(w * 4 + r) * HID + 128 + lane * 4] = *(float4*)&o[4];
    }
    __syncwarp();

    float m[4];
    float mb = 32.f * b2[lane];
#pragma unroll
    for (int r = 0; r < 4; r++) m[r] = mb;
#pragma unroll 4
    for (int hh = 0; hh < HID; hh += 4) {
        float4 wv = *(const float4*)&s_w2[lane * W2STR + hh];
#pragma unroll
        for (int r = 0; r < 4; r++) {
            float4 sv = *(const float4*)&s_S[(w * 4 + r) * HID + hh];
            m[r] = fmaf(sv.x, wv.x, m[r]);
            m[r] = fmaf(sv.y, wv.y, m[r]);
            m[r] = fmaf(sv.z, wv.z, m[r]);
            m[r] = fmaf(sv.w, wv.w, m[r]);
        }
    }
#pragma unroll
    for (int r = 0; r < 4; r++) {
        float mx = sc[r];
#pragma unroll
        for (int o = 16; o > 0; o >>= 1) mx = fmaxf(mx, __shfl_xor_sync(0xffffffffu, mx, o));
        float e = __expf(sc[r] - mx);
        float se = e;
#pragma unroll
        for (int o = 16; o > 0; o >>= 1) se += __shfl_xor_sync(0xffffffffu, se, o);
        out[(size_t)(b0 + r) * NA + lane] = qv[r] + (e / se) * m[r];
    }
}

// ======================= launch =======================
extern "C" void kernel_launch(void* const* d_in, const int* in_sizes, int n_in,
                              void* d_out, int out_size) {
    const float* h   = (const float*)d_in[0];
    const float* act = (const float*)d_in[1];
    const float* qfw = (const float*)d_in[2];
    const float* qfb = (const float*)d_in[3];
    const float* w1  = (const float*)d_in[4];
    const float* b1  = (const float*)d_in[5];
    const float* w2  = (const float*)d_in[6];
    const float* b2  = (const float*)d_in[7];
    const float* kw  = (const float*)d_in[8];
    const float* kb  = (const float*)d_in[9];
    const float* qw  = (const float*)d_in[10];
    const float* qb  = (const float*)d_in[11];
    float* out = (float*)d_out;
    (void)in_sizes; (void)n_in; (void)out_size;

    cudaFuncSetAttribute(gemm_mma_kernel, cudaFuncAttributeMaxDynamicSharedMemorySize, GEMM_SMEM);
    cudaFuncSetAttribute(epilogue_kernel, cudaFuncAttributeMaxDynamicSharedMemorySize, EPI_SMEM);

    setup1_kernel<<<1, 256>>>(act, qfb, kb, qw, qb);
    setup2_kernel<<<64, 256>>>(act, qfw, w1, b1, kw);
    apack_kernel<<<NB * RNN / 8 / 256, 256>>>(h);
    dim3 ggrid(NF / 64, NB / 128);
    gemm_mma_kernel<<<ggrid, 256, GEMM_SMEM>>>();
    epilogue_kernel<<<NB / 32, 256, EPI_SMEM>>>(w2, b2, out);
}